// round 12
// baseline (speedup 1.0000x reference)
#include <cuda_runtime.h>
#include <math.h>
#include <stdint.h>

#define B_SAMPLES 512
#define M_ROWS    24
#define D_DIM     4096
#define CHUNK     128                 // floats of K per stage
#define NSTAGE    (D_DIM / CHUNK)     // 32
#define THREADS   256                 // 8 warps
#define NW        8
#define GRID      B_SAMPLES
#define P         132                 // smem row pitch (floats): bank-spread
#define STAGEF    (M_ROWS * P)        // 3168 floats
#define SLOT_B    (STAGEF * 4)        // 12672 bytes
#define DEPTH     4
#define RING_B    (DEPTH * SLOT_B)    // 50688 bytes dynamic smem
#define GP        25                  // G row pitch

__device__ float        g_scratch[B_SAMPLES];
__device__ unsigned int g_count = 0;

__device__ __forceinline__ unsigned int smem_u32(const void* p) {
    unsigned int a;
    asm("{ .reg .u64 t; cvta.to.shared.u64 t, %1; cvt.u32.u64 %0, t; }" : "=r"(a) : "l"(p));
    return a;
}
__device__ __forceinline__ void cp16(unsigned int dst, const float* src) {
    asm volatile("cp.async.cg.shared.global [%0], [%1], 16;" :: "r"(dst), "l"(src));
}
__device__ __forceinline__ void cp_commit() { asm volatile("cp.async.commit_group;"); }
__device__ __forceinline__ void cp_wait2()  { asm volatile("cp.async.wait_group 2;"); }
__device__ __forceinline__ float lds32(unsigned int a) {
    float v;
    asm volatile("ld.shared.f32 %0, [%1];" : "=f"(v) : "r"(a));
    return v;
}
__device__ __forceinline__ uint32_t f2tf(float f) {
    uint32_t u;
    asm("cvt.rna.tf32.f32 %0, %1;" : "=r"(u) : "f"(f));
    return u;
}
__device__ __forceinline__ void mma8(float* d, uint32_t a0, uint32_t a1,
                                     uint32_t a2, uint32_t a3,
                                     uint32_t b0, uint32_t b1) {
    asm volatile(
        "mma.sync.aligned.m16n8k8.row.col.f32.tf32.tf32.f32 "
        "{%0,%1,%2,%3}, {%4,%5,%6,%7}, {%8,%9}, {%0,%1,%2,%3};"
        : "+f"(d[0]), "+f"(d[1]), "+f"(d[2]), "+f"(d[3])
        : "r"(a0), "r"(a1), "r"(a2), "r"(a3), "r"(b0), "r"(b1));
}

__global__ __launch_bounds__(THREADS)
void gram_mma_kernel(const float* __restrict__ feat, float* __restrict__ out) {
    extern __shared__ float ring[];            // DEPTH slots of [24][P]
    __shared__ float sinv[M_ROWS];
    __shared__ float marr[M_ROWS];
    __shared__ float sred[THREADS];
    __shared__ int   s_last;

    const int tid  = threadIdx.x;
    const int ws   = tid >> 5;            // warp = split-K slice (0..7)
    const int lane = tid & 31;
    const int gid  = lane >> 2;           // fragment row in group (0..7)
    const int q    = lane & 3;            // fragment quad col (0..3)
    const int b    = blockIdx.x;
    const float* base = feat + (size_t)b * (M_ROWS * D_DIM);
    const unsigned int rb0 = smem_u32(ring);

    float acc00[4] = {0,0,0,0}, acc01[4] = {0,0,0,0};
    float acc02[4] = {0,0,0,0}, acc11[4] = {0,0,0,0};

    // lane-invariant byte offsets within a slot (rows gid, gid+8, gid+16)
    const unsigned int o0 = 4u * (unsigned)(gid * P + q);
    const unsigned int o1 = o0 + 4u * (unsigned)(8 * P);
    const unsigned int o2 = o0 + 4u * (unsigned)(16 * P);

    // ---- staging: 768 float4 per stage over 256 threads (3 each) ----
    auto issue_stage = [&](int st) {
        const unsigned int slot = rb0 + (unsigned)((st & (DEPTH - 1)) * SLOT_B);
        const float* src = base + st * CHUNK;
#pragma unroll
        for (int i = 0; i < 3; i++) {
            int e = tid + i * THREADS;            // 0..767
            int r = e >> 5, c = e & 31;           // row, float4 col
            cp16(slot + 4u * (unsigned)(r * P + c * 4),
                 src + (size_t)r * D_DIM + c * 4);
        }
    };

    issue_stage(0); cp_commit();
    issue_stage(1); cp_commit();
    issue_stage(2); cp_commit();

    // ---- main loop: depth-3 prefetch, 1 barrier/stage ----
    for (int s = 0; s < NSTAGE; ++s) {
        cp_wait2();                      // stage s's group retired
        __syncthreads();                 // stage s visible; slot (s+3)%4 free
        if (s + 3 < NSTAGE) issue_stage(s + 3);
        cp_commit();                     // empty commit keeps group accounting

        const unsigned int slot = rb0 + (unsigned)((s & (DEPTH - 1)) * SLOT_B);
#pragma unroll
        for (int j = 0; j < 2; ++j) {
            const unsigned int ko = 4u * (unsigned)((ws + NW * j) * 8);  // bytes
            uint32_t a0 = f2tf(lds32(slot + o0 + ko));
            uint32_t a2 = f2tf(lds32(slot + o0 + ko + 16u));
            uint32_t a1 = f2tf(lds32(slot + o1 + ko));
            uint32_t a3 = f2tf(lds32(slot + o1 + ko + 16u));
            uint32_t t0 = f2tf(lds32(slot + o2 + ko));
            uint32_t t2 = f2tf(lds32(slot + o2 + ko + 16u));
            mma8(acc00, a0, a1, a2, a3, a0, a2);   // G[0:16,  0:8 ]
            mma8(acc01, a0, a1, a2, a3, a1, a3);   // G[0:16,  8:16]
            mma8(acc02, a0, a1, a2, a3, t0, t2);   // G[0:16, 16:24]
            mma8(acc11, t0, 0u, t2, 0u, t0, t2);   // G[16:24,16:24]
        }
    }
    __syncthreads();   // all warps done with ring before overlay

    // ---- per-warp partials -> overlay on ring (8 x 600 floats) ----
    {
        float* gp = ring + ws * (M_ROWS * GP);
        gp[gid * GP + 2*q]             = acc00[0];
        gp[gid * GP + 2*q + 1]         = acc00[1];
        gp[(gid+8) * GP + 2*q]         = acc00[2];
        gp[(gid+8) * GP + 2*q + 1]     = acc00[3];
        gp[gid * GP + 8 + 2*q]         = acc01[0];
        gp[gid * GP + 8 + 2*q + 1]     = acc01[1];
        gp[(gid+8) * GP + 8 + 2*q]     = acc01[2];
        gp[(gid+8) * GP + 8 + 2*q + 1] = acc01[3];
        gp[gid * GP + 16 + 2*q]        = acc02[0];
        gp[gid * GP + 16 + 2*q + 1]    = acc02[1];
        gp[(gid+8) * GP + 16 + 2*q]    = acc02[2];
        gp[(gid+8) * GP + 16 + 2*q+1]  = acc02[3];
        gp[(16+gid) * GP + 16 + 2*q]   = acc11[0];
        gp[(16+gid) * GP + 16 + 2*q+1] = acc11[1];
    }
    __syncthreads();

    // ---- sum 8 split-K partials (448 valid entries) ----
    for (int e = tid; e < 448; e += THREADS) {
        int r, c;
        if (e < 384) { r = e / 24; c = e % 24; }
        else { int f = e - 384; r = 16 + f / 8; c = 16 + f % 8; }
        float v = 0.f;
#pragma unroll
        for (int w = 0; w < NW; w++) v += ring[w * (M_ROWS * GP) + r * GP + c];
        ring[r * GP + c] = v;
    }
    __syncthreads();

    // ---- norms ----
    if (tid < M_ROWS) {
        float nr = sqrtf(ring[tid * GP + tid]);
        sinv[tid] = 1.0f / fmaxf(nr, 1e-12f);
    }
    __syncthreads();

    // ---- per-anchor masked log-softmax (reference: no max subtraction) ----
    if (tid < M_ROWS) {
        const int m = tid;
        const float im = sinv[m];
        const int cm = m % 12;
        float denom = 0.f, possum = 0.f, cnt = 0.f;
#pragma unroll
        for (int n = 0; n < M_ROWS; ++n) {
            if (n == m) continue;
            float gv = (m < 16 || n >= 16) ? ring[m * GP + n] : ring[n * GP + m];
            float logit = gv * im * sinv[n] * 10.0f;   // /T, T=0.1
            denom += expf(logit);
            int dc = cm - (n % 12); if (dc < 0) dc = -dc;
            if (dc <= 1) { possum += logit; cnt += 1.f; }
        }
        marr[m] = (possum - cnt * logf(denom)) / (cnt + 1e-6f);
    }
    __syncthreads();
    if (tid == 0) {
        float s = 0.f;
#pragma unroll
        for (int n = 0; n < M_ROWS; n++) s += marr[n];
        g_scratch[b] = s * (-0.1f / 24.0f);
    }

    // ---- fused deterministic final reduction (last CTA) ----
    if (tid == 0) {
        __threadfence();
        unsigned int old = atomicAdd(&g_count, 1u);
        s_last = (old == GRID - 1) ? 1 : 0;
    }
    __syncthreads();
    if (s_last) {
        __threadfence();
        sred[tid] = g_scratch[tid] + g_scratch[tid + 256];
        __syncthreads();
#pragma unroll
        for (int w = 128; w > 0; w >>= 1) {
            if (tid < w) sred[tid] += sred[tid + w];
            __syncthreads();
        }
        if (tid == 0) {
            out[0] = sred[0] * (1.0f / (float)B_SAMPLES);
            g_count = 0;   // reset for next graph replay
        }
    }
}

extern "C" void kernel_launch(void* const* d_in, const int* in_sizes, int n_in,
                              void* d_out, int out_size) {
    const float* feat = (const float*)d_in[2];
    static int configured = 0;
    if (!configured) {
        cudaFuncSetAttribute(gram_mma_kernel,
                             cudaFuncAttributeMaxDynamicSharedMemorySize, RING_B);
        configured = 1;
    }
    gram_mma_kernel<<<GRID, THREADS, RING_B>>>(feat, (float*)d_out);
}